// round 1
// baseline (speedup 1.0000x reference)
#include <cuda_runtime.h>
#include <math.h>
#include <float.h>

#define Bn   4
#define Hn   32
#define HKV  8
#define Gn   4
#define Dn   128
#define Pn   128
#define Sn   64
#define KP   16
#define NEGV (-1000000000.0f)
#define SM_SCALE 0.08838834764831845f

// Scratch (allocation-free rule: __device__ globals)
__device__ float g_q_rope[Bn*Hn*Dn];
__device__ float g_k_rope[Bn*HKV*Dn];
__device__ float g_scores[Bn*Hn*Pn*Sn];   // 4 MB full masked score matrix
__device__ float g_stats [Bn*Hn*Pn];      // per-page max
__device__ int   g_sel   [Bn*Hn*KP];
__device__ float g_cur   [Bn*Hn];

// ---------------------------------------------------------------- kernel 0
// RoPE (neox) for q (B*H heads) and current k (B*HKV heads). 64 threads/blk.
__global__ void rope_kernel(const float* __restrict__ q,
                            const float* __restrict__ k,
                            const int*   __restrict__ timestep)
{
    int i = blockIdx.x;          // 0..159
    int t = threadIdx.x;         // 0..63 (half = D/2)
    float pos = (float)(timestep[0] - 1);
    float inv = 1.0f / powf(10000.0f, (float)t * (2.0f / (float)Dn));
    float ang = pos * inv;
    float c = cosf(ang), s = sinf(ang);

    const float* src;
    float* dst;
    if (i < Bn*Hn) { src = q + (size_t)i*Dn;          dst = g_q_rope + (size_t)i*Dn; }
    else           { src = k + (size_t)(i-Bn*Hn)*Dn;  dst = g_k_rope + (size_t)(i-Bn*Hn)*Dn; }

    float x1 = src[t], x2 = src[t+64];
    dst[t]      = x1*c - x2*s;
    dst[t+64]   = x1*s + x2*c;
}

// ---------------------------------------------------------------- kernel 1
// One block per (page, b*HKV). 128 threads: 2 threads per token (D split).
// Writes masked*scaled scores for all G heads + per-page max stats.
__global__ void score_kernel(const int*   __restrict__ k_cache,
                             const float* __restrict__ kv_scale,
                             const int*   __restrict__ lengths)
{
    int p   = blockIdx.x;
    int bh  = blockIdx.y;            // b*HKV + hkv
    int b   = bh / HKV, hkv = bh % HKV;
    int tid = threadIdx.x;           // 128
    int len = max(lengths[b], 1);
    int head0 = b*Hn + hkv*Gn;

    if (p*Sn >= len) {
        // fully masked page: write NEG scores (page P-1 may be force-selected)
        if (tid < Sn) {
            #pragma unroll
            for (int g = 0; g < Gn; g++)
                g_scores[(size_t)(head0+g)*Pn*Sn + p*Sn + tid] = NEGV;
        }
        if (tid < Gn) g_stats[(head0+tid)*Pn + p] = NEGV;
        return;
    }

    __shared__ float4 qs4[Gn][Dn/4];
    {
        float* qf = (float*)qs4;
        #pragma unroll
        for (int g = 0; g < Gn; g++)
            qf[g*Dn + tid] = g_q_rope[(size_t)(head0+g)*Dn + tid];
    }
    __syncthreads();

    float sk_scale = kv_scale[0] * SM_SCALE;

    int s    = tid >> 1;
    int half = tid & 1;
    int d0   = half * 64;
    const int4* kp = (const int4*)(k_cache +
        ((((size_t)b*Pn + p)*Sn + s)*HKV + hkv)*Dn + d0);

    float a0=0.f, a1=0.f, a2=0.f, a3=0.f;
    int q4base = d0 >> 2;
    #pragma unroll
    for (int j = 0; j < 16; j++) {
        int4 kv = kp[j];
        float f0=(float)kv.x, f1=(float)kv.y, f2=(float)kv.z, f3=(float)kv.w;
        float4 q0 = qs4[0][q4base+j];
        float4 q1 = qs4[1][q4base+j];
        float4 q2 = qs4[2][q4base+j];
        float4 q3 = qs4[3][q4base+j];
        a0 += f0*q0.x + f1*q0.y + f2*q0.z + f3*q0.w;
        a1 += f0*q1.x + f1*q1.y + f2*q1.z + f3*q1.w;
        a2 += f0*q2.x + f1*q2.y + f2*q2.z + f3*q2.w;
        a3 += f0*q3.x + f1*q3.y + f2*q3.z + f3*q3.w;
    }

    // combine the two D-halves (lanes 2s and 2s+1)
    a0 += __shfl_xor_sync(0xffffffffu, a0, 1);
    a1 += __shfl_xor_sync(0xffffffffu, a1, 1);
    a2 += __shfl_xor_sync(0xffffffffu, a2, 1);
    a3 += __shfl_xor_sync(0xffffffffu, a3, 1);

    int pos = p*Sn + s;
    bool valid = pos < len;
    float sc[4];
    sc[0] = valid ? a0*sk_scale : NEGV;
    sc[1] = valid ? a1*sk_scale : NEGV;
    sc[2] = valid ? a2*sk_scale : NEGV;
    sc[3] = valid ? a3*sk_scale : NEGV;

    if (half == 0) {
        #pragma unroll
        for (int g = 0; g < Gn; g++)
            g_scores[(size_t)(head0+g)*Pn*Sn + p*Sn + s] = sc[g];
    }

    // per-page max per g (warp reduce over 16 tokens x 2 halves, then 4 warps)
    __shared__ float wmax[4][Gn];
    int warp = tid >> 5, lane = tid & 31;
    #pragma unroll
    for (int g = 0; g < Gn; g++) {
        float v = sc[g];
        #pragma unroll
        for (int o = 16; o >= 1; o >>= 1)
            v = fmaxf(v, __shfl_xor_sync(0xffffffffu, v, o));
        if (lane == 0) wmax[warp][g] = v;
    }
    __syncthreads();
    if (tid < Gn) {
        float v = fmaxf(fmaxf(wmax[0][tid], wmax[1][tid]),
                        fmaxf(wmax[2][tid], wmax[3][tid]));
        g_stats[(head0+tid)*Pn + p] = v;
    }
}

// ---------------------------------------------------------------- kernel 2
// Per head: top-15 of stats[0..126] (jax.lax.top_k semantics) + page 127,
// plus current-token score. 128 threads, 128 blocks.
__device__ __forceinline__ unsigned int fkey(float f) {
    unsigned int b = __float_as_uint(f);
    return b ^ ((b & 0x80000000u) ? 0xFFFFFFFFu : 0x80000000u);
}

__global__ void topk_kernel(float* __restrict__ out_idx, int write_idx)
{
    __shared__ unsigned long long sw[4];
    __shared__ float sf[4];
    __shared__ int s_sel[KP];

    int head = blockIdx.x;
    int tid  = threadIdx.x;
    int b = head / Hn, h = head % Hn, hkv = h / Gn;
    int warp = tid >> 5, lane = tid & 31;

    // current-token score: dot(q_rope, k_rope) * sm_scale
    float prod = g_q_rope[(size_t)head*Dn + tid] *
                 g_k_rope[(size_t)(b*HKV + hkv)*Dn + tid];
    #pragma unroll
    for (int o = 16; o >= 1; o >>= 1)
        prod += __shfl_xor_sync(0xffffffffu, prod, o);
    if (lane == 0) sf[warp] = prod;
    __syncthreads();
    if (tid == 0) g_cur[head] = (sf[0]+sf[1]+sf[2]+sf[3]) * SM_SCALE;

    // top-k keys: (monotone float, ~idx) so max key = (max val, min idx)
    unsigned long long mykey = 0ull;
    if (tid < Pn-1)
        mykey = ((unsigned long long)fkey(g_stats[head*Pn + tid]) << 32)
              | (unsigned int)(~tid);

    for (int it = 0; it < KP-1; it++) {
        unsigned long long v = mykey;
        #pragma unroll
        for (int o = 16; o >= 1; o >>= 1) {
            unsigned long long u = __shfl_xor_sync(0xffffffffu, v, o);
            v = (u > v) ? u : v;
        }
        if (lane == 0) sw[warp] = v;
        __syncthreads();
        if (tid == 0) {
            unsigned long long m = sw[0];
            #pragma unroll
            for (int i = 1; i < 4; i++) m = (sw[i] > m) ? sw[i] : m;
            sw[0] = m;
        }
        __syncthreads();
        unsigned long long best = sw[0];
        __syncthreads();
        int idx = (int)(~(unsigned int)(best & 0xFFFFFFFFull));
        if (tid == idx) mykey = 0ull;
        if (tid == 0) s_sel[it] = idx;
    }
    __syncthreads();

    if (tid < KP) {
        int v = (tid == KP-1) ? (Pn-1) : s_sel[tid];
        g_sel[head*KP + tid] = v;
        if (write_idx) out_idx[head*KP + tid] = (float)v;
    }
}

// ---------------------------------------------------------------- kernel 3
// Per head: gather selected scores, softmax, weighted V sum (+current token).
// 128 threads: 4 token-groups x 32 lanes, int4 V loads (lane -> 4 d's).
__global__ void attn_kernel(const int*   __restrict__ v_cache,
                            const float* __restrict__ v_cur,
                            const float* __restrict__ kv_scale,
                            float* __restrict__ out)
{
    __shared__ int    pages[KP];
    __shared__ float  w[KP*Sn + 1];
    __shared__ float  red[4];
    __shared__ float4 part[4][32];

    int head = blockIdx.x;
    int tid  = threadIdx.x;
    int b = head / Hn, h = head % Hn, hkv = h / Gn;
    int warp = tid >> 5, lane = tid & 31;

    if (tid < KP) pages[tid] = g_sel[head*KP + tid];
    __syncthreads();

    const float* sc = g_scores + (size_t)head*Pn*Sn;
    for (int t = tid; t < KP*Sn; t += 128)
        w[t] = sc[pages[t >> 6]*Sn + (t & 63)];
    if (tid == 0) w[KP*Sn] = g_cur[head];
    __syncthreads();

    // softmax: max
    float m = -FLT_MAX;
    for (int t = tid; t <= KP*Sn; t += 128) m = fmaxf(m, w[t]);
    #pragma unroll
    for (int o = 16; o >= 1; o >>= 1)
        m = fmaxf(m, __shfl_xor_sync(0xffffffffu, m, o));
    if (lane == 0) red[warp] = m;
    __syncthreads();
    m = fmaxf(fmaxf(red[0], red[1]), fmaxf(red[2], red[3]));
    __syncthreads();

    // exp + sum
    float ss = 0.f;
    for (int t = tid; t <= KP*Sn; t += 128) {
        float e = expf(w[t] - m);
        w[t] = e;
        ss += e;
    }
    #pragma unroll
    for (int o = 16; o >= 1; o >>= 1)
        ss += __shfl_xor_sync(0xffffffffu, ss, o);
    if (lane == 0) red[warp] = ss;
    __syncthreads();
    float total = red[0] + red[1] + red[2] + red[3];

    // V accumulation: group = warp handles tokens s == group (mod 4)
    int grp = warp;
    float a0=0.f, a1=0.f, a2=0.f, a3=0.f;
    for (int kp = 0; kp < KP; kp++) {
        const int4* vp = (const int4*)(v_cache +
            (((size_t)(b*Pn + pages[kp])*Sn)*HKV + hkv)*Dn) + lane;
        const float* wp = w + kp*Sn;
        #pragma unroll
        for (int s2 = 0; s2 < Sn/4; s2++) {
            int srow = s2*4 + grp;
            int4 vv = vp[(size_t)srow * (HKV*Dn/4)];
            float ww = wp[srow];
            a0 += ww*(float)vv.x; a1 += ww*(float)vv.y;
            a2 += ww*(float)vv.z; a3 += ww*(float)vv.w;
        }
    }
    part[grp][lane] = make_float4(a0, a1, a2, a3);
    __syncthreads();

    int d = tid;
    int lane2 = d >> 2, comp = d & 3;
    float acc = 0.f;
    #pragma unroll
    for (int g2 = 0; g2 < 4; g2++) {
        float4 pv = part[g2][lane2];
        acc += (comp==0) ? pv.x : (comp==1) ? pv.y : (comp==2) ? pv.z : pv.w;
    }
    acc *= kv_scale[1];
    acc += w[KP*Sn] * v_cur[(size_t)(b*HKV + hkv)*Dn + d];
    out[(size_t)head*Dn + d] = acc / total;
}

// ---------------------------------------------------------------- launch
extern "C" void kernel_launch(void* const* d_in, const int* in_sizes, int n_in,
                              void* d_out, int out_size)
{
    const float* q        = (const float*)d_in[0];
    const float* k        = (const float*)d_in[1];
    const float* v        = (const float*)d_in[2];
    const float* kv_scale = (const float*)d_in[3];
    const int*   k_cache  = (const int*)  d_in[4];
    const int*   v_cache  = (const int*)  d_in[5];
    const int*   lengths  = (const int*)  d_in[6];
    const int*   timestep = (const int*)  d_in[7];
    float* out = (float*)d_out;

    int write_idx = (out_size >= Bn*Hn*Dn + Bn*Hn*KP) ? 1 : 0;

    rope_kernel<<<Bn*Hn + Bn*HKV, 64>>>(q, k, timestep);
    score_kernel<<<dim3(Pn, Bn*HKV), 128>>>(k_cache, kv_scale, lengths);
    topk_kernel<<<Bn*Hn, 128>>>(out + Bn*Hn*Dn, write_idx);
    attn_kernel<<<Bn*Hn, 128>>>(v_cache, v, kv_scale, out);
}

// round 2
// speedup vs baseline: 1.5676x; 1.5676x over previous
#include <cuda_runtime.h>
#include <math.h>
#include <float.h>

#define Bn   4
#define Hn   32
#define HKV  8
#define Gn   4
#define Dn   128
#define Pn   128
#define Sn   64
#define KP   16
#define NEGV (-1000000000.0f)
#define SM_SCALE 0.08838834764831845f

// Scratch (allocation-free rule: __device__ globals)
__device__ float g_q_rope[Bn*Hn*Dn];
__device__ float g_k_rope[Bn*HKV*Dn];
__device__ float g_scores[Bn*Hn*Pn*Sn];   // 4 MB full masked score matrix
__device__ float g_stats [Bn*Hn*Pn];      // per-page max
__device__ int   g_sel   [Bn*Hn*KP];
__device__ float g_cur   [Bn*Hn];         // current-token score
__device__ float g_max   [Bn*Hn];         // softmax max per head
__device__ float g_part  [Bn*Hn*KP*Dn];   // per-(head,page) partial sum(exp*V)
__device__ float g_pden  [Bn*Hn*KP];      // per-(head,page) partial denom

// ---------------------------------------------------------------- kernel 0
// RoPE (neox) for q (B*H heads) and current k (B*HKV heads). 64 threads/blk.
__global__ void rope_kernel(const float* __restrict__ q,
                            const float* __restrict__ k,
                            const int*   __restrict__ timestep)
{
    int i = blockIdx.x;          // 0..159
    int t = threadIdx.x;         // 0..63 (half = D/2)
    float pos = (float)(timestep[0] - 1);
    float inv = 1.0f / powf(10000.0f, (float)t * (2.0f / (float)Dn));
    float ang = pos * inv;
    float c = cosf(ang), s = sinf(ang);

    const float* src;
    float* dst;
    if (i < Bn*Hn) { src = q + (size_t)i*Dn;          dst = g_q_rope + (size_t)i*Dn; }
    else           { src = k + (size_t)(i-Bn*Hn)*Dn;  dst = g_k_rope + (size_t)(i-Bn*Hn)*Dn; }

    float x1 = src[t], x2 = src[t+64];
    dst[t]      = x1*c - x2*s;
    dst[t+64]   = x1*s + x2*c;
}

// ---------------------------------------------------------------- kernel 1
// One block per (page, b*HKV). 128 threads: 2 threads per token (D split).
// Writes masked*scaled scores for all G heads + per-page max stats.
__global__ void score_kernel(const int*   __restrict__ k_cache,
                             const float* __restrict__ kv_scale,
                             const int*   __restrict__ lengths)
{
    int p   = blockIdx.x;
    int bh  = blockIdx.y;            // b*HKV + hkv
    int b   = bh / HKV, hkv = bh % HKV;
    int tid = threadIdx.x;           // 128
    int len = max(lengths[b], 1);
    int head0 = b*Hn + hkv*Gn;

    if (p*Sn >= len) {
        // fully masked page: write NEG scores (page P-1 may be force-selected)
        if (tid < Sn) {
            #pragma unroll
            for (int g = 0; g < Gn; g++)
                g_scores[(size_t)(head0+g)*Pn*Sn + p*Sn + tid] = NEGV;
        }
        if (tid < Gn) g_stats[(head0+tid)*Pn + p] = NEGV;
        return;
    }

    __shared__ float4 qs4[Gn][Dn/4];
    {
        float* qf = (float*)qs4;
        #pragma unroll
        for (int g = 0; g < Gn; g++)
            qf[g*Dn + tid] = g_q_rope[(size_t)(head0+g)*Dn + tid];
    }
    __syncthreads();

    float sk_scale = kv_scale[0] * SM_SCALE;

    int s    = tid >> 1;
    int half = tid & 1;
    int d0   = half * 64;
    const int4* kp = (const int4*)(k_cache +
        ((((size_t)b*Pn + p)*Sn + s)*HKV + hkv)*Dn + d0);

    float a0=0.f, a1=0.f, a2=0.f, a3=0.f;
    int q4base = d0 >> 2;
    #pragma unroll
    for (int j = 0; j < 16; j++) {
        int4 kv = kp[j];
        float f0=(float)kv.x, f1=(float)kv.y, f2=(float)kv.z, f3=(float)kv.w;
        float4 q0 = qs4[0][q4base+j];
        float4 q1 = qs4[1][q4base+j];
        float4 q2 = qs4[2][q4base+j];
        float4 q3 = qs4[3][q4base+j];
        a0 += f0*q0.x + f1*q0.y + f2*q0.z + f3*q0.w;
        a1 += f0*q1.x + f1*q1.y + f2*q1.z + f3*q1.w;
        a2 += f0*q2.x + f1*q2.y + f2*q2.z + f3*q2.w;
        a3 += f0*q3.x + f1*q3.y + f2*q3.z + f3*q3.w;
    }

    // combine the two D-halves (lanes 2s and 2s+1)
    a0 += __shfl_xor_sync(0xffffffffu, a0, 1);
    a1 += __shfl_xor_sync(0xffffffffu, a1, 1);
    a2 += __shfl_xor_sync(0xffffffffu, a2, 1);
    a3 += __shfl_xor_sync(0xffffffffu, a3, 1);

    int pos = p*Sn + s;
    bool valid = pos < len;
    float sc[4];
    sc[0] = valid ? a0*sk_scale : NEGV;
    sc[1] = valid ? a1*sk_scale : NEGV;
    sc[2] = valid ? a2*sk_scale : NEGV;
    sc[3] = valid ? a3*sk_scale : NEGV;

    if (half == 0) {
        #pragma unroll
        for (int g = 0; g < Gn; g++)
            g_scores[(size_t)(head0+g)*Pn*Sn + p*Sn + s] = sc[g];
    }

    // per-page max per g (warp reduce over 16 tokens x 2 halves, then 4 warps)
    __shared__ float wmax[4][Gn];
    int warp = tid >> 5, lane = tid & 31;
    #pragma unroll
    for (int g = 0; g < Gn; g++) {
        float v = sc[g];
        #pragma unroll
        for (int o = 16; o >= 1; o >>= 1)
            v = fmaxf(v, __shfl_xor_sync(0xffffffffu, v, o));
        if (lane == 0) wmax[warp][g] = v;
    }
    __syncthreads();
    if (tid < Gn) {
        float v = fmaxf(fmaxf(wmax[0][tid], wmax[1][tid]),
                        fmaxf(wmax[2][tid], wmax[3][tid]));
        g_stats[(head0+tid)*Pn + p] = v;
    }
}

// ---------------------------------------------------------------- kernel 2
// Per head: top-15 of stats[0..126] (jax.lax.top_k semantics) + page 127,
// plus current-token score and global softmax max. 128 threads, 128 blocks.
__device__ __forceinline__ unsigned int fkey(float f) {
    unsigned int b = __float_as_uint(f);
    return b ^ ((b & 0x80000000u) ? 0xFFFFFFFFu : 0x80000000u);
}

__global__ void topk_kernel(float* __restrict__ out_idx, int write_idx)
{
    __shared__ unsigned long long sw[4];
    __shared__ float sf[4];
    __shared__ int s_sel[KP];

    int head = blockIdx.x;
    int tid  = threadIdx.x;
    int b = head / Hn, h = head % Hn, hkv = h / Gn;
    int warp = tid >> 5, lane = tid & 31;

    // current-token score: dot(q_rope, k_rope) * sm_scale
    float prod = g_q_rope[(size_t)head*Dn + tid] *
                 g_k_rope[(size_t)(b*HKV + hkv)*Dn + tid];
    #pragma unroll
    for (int o = 16; o >= 1; o >>= 1)
        prod += __shfl_xor_sync(0xffffffffu, prod, o);
    if (lane == 0) sf[warp] = prod;
    __syncthreads();
    float curv = (sf[0]+sf[1]+sf[2]+sf[3]) * SM_SCALE;
    if (tid == 0) g_cur[head] = curv;

    // top-k keys: (monotone float, ~idx) so max key = (max val, min idx)
    unsigned long long mykey = 0ull;
    if (tid < Pn-1)
        mykey = ((unsigned long long)fkey(g_stats[head*Pn + tid]) << 32)
              | (unsigned int)(~tid);

    for (int it = 0; it < KP-1; it++) {
        unsigned long long v = mykey;
        #pragma unroll
        for (int o = 16; o >= 1; o >>= 1) {
            unsigned long long u = __shfl_xor_sync(0xffffffffu, v, o);
            v = (u > v) ? u : v;
        }
        if (lane == 0) sw[warp] = v;
        __syncthreads();
        if (tid == 0) {
            unsigned long long m = sw[0];
            #pragma unroll
            for (int i = 1; i < 4; i++) m = (sw[i] > m) ? sw[i] : m;
            sw[0] = m;
        }
        __syncthreads();
        unsigned long long best = sw[0];
        __syncthreads();
        int idx = (int)(~(unsigned int)(best & 0xFFFFFFFFull));
        if (tid == idx) mykey = 0ull;
        if (tid == 0) s_sel[it] = idx;
    }
    __syncthreads();

    if (tid < KP) {
        int v = (tid == KP-1) ? (Pn-1) : s_sel[tid];
        g_sel[head*KP + tid] = v;
        if (write_idx) out_idx[head*KP + tid] = (float)v;
    }
    if (tid == 0) {
        // softmax max: stats of top page dominates all selected scores;
        // forced page 127 and current token can exceed it.
        float m = g_stats[head*Pn + s_sel[0]];
        m = fmaxf(m, g_stats[head*Pn + (Pn-1)]);
        m = fmaxf(m, curv);
        g_max[head] = m;
    }
}

// ---------------------------------------------------------------- kernel 3
// One block per (head, selected page): 2048 blocks x 128 threads.
// Computes partial sum(exp(score-m) * V) over 64 tokens + partial denom.
__global__ void attn_part_kernel(const int* __restrict__ v_cache)
{
    __shared__ float  w[Sn];
    __shared__ float4 part[4][32];

    int bid  = blockIdx.x;
    int head = bid >> 4;
    int kp   = bid & (KP-1);
    int tid  = threadIdx.x;
    int warp = tid >> 5, lane = tid & 31;
    int b = head >> 5;                 // head / Hn
    int hkv = (head & (Hn-1)) >> 2;    // (head % Hn) / Gn

    int page = g_sel[head*KP + kp];
    float m  = g_max[head];

    if (tid < Sn)
        w[tid] = expf(g_scores[(size_t)head*Pn*Sn + page*Sn + tid] - m);
    __syncthreads();

    // partial denom (warp 0)
    if (warp == 0) {
        float s = w[lane] + w[lane + 32];
        #pragma unroll
        for (int o = 16; o >= 1; o >>= 1)
            s += __shfl_xor_sync(0xffffffffu, s, o);
        if (lane == 0) g_pden[head*KP + kp] = s;
    }

    // V accumulation: warp g handles tokens s == g (mod 4); lane -> 4 dims
    const int4* vp = (const int4*)(v_cache +
        (((size_t)(b*Pn + page)*Sn)*HKV + hkv)*Dn) + lane;
    float a0=0.f, a1=0.f, a2=0.f, a3=0.f;
    #pragma unroll
    for (int s2 = 0; s2 < Sn/4; s2++) {
        int srow = s2*4 + warp;
        int4 vv = vp[(size_t)srow * (HKV*Dn/4)];
        float ww = w[srow];
        a0 += ww*(float)vv.x; a1 += ww*(float)vv.y;
        a2 += ww*(float)vv.z; a3 += ww*(float)vv.w;
    }
    part[warp][lane] = make_float4(a0, a1, a2, a3);
    __syncthreads();

    int lane2 = tid >> 2, comp = tid & 3;
    float acc = 0.f;
    #pragma unroll
    for (int g2 = 0; g2 < 4; g2++) {
        float4 pv = part[g2][lane2];
        acc += (comp==0) ? pv.x : (comp==1) ? pv.y : (comp==2) ? pv.z : pv.w;
    }
    g_part[((size_t)head*KP + kp)*Dn + tid] = acc;
}

// ---------------------------------------------------------------- kernel 4
// Per head: sum 16 partials, add current token, normalize. 128 blocks x 128.
__global__ void attn_reduce_kernel(const float* __restrict__ v_cur,
                                   const float* __restrict__ kv_scale,
                                   float* __restrict__ out)
{
    int head = blockIdx.x;
    int tid  = threadIdx.x;
    int b = head >> 5;
    int hkv = (head & (Hn-1)) >> 2;

    float acc = 0.f;
    const float* pp = g_part + (size_t)head*KP*Dn + tid;
    #pragma unroll
    for (int kp = 0; kp < KP; kp++)
        acc += pp[kp*Dn];

    float m    = g_max[head];
    float ecur = expf(g_cur[head] - m);

    float den = ecur;
    const float* dp = g_pden + head*KP;
    #pragma unroll
    for (int kp = 0; kp < KP; kp++)
        den += dp[kp];

    float o = acc * kv_scale[1] + ecur * v_cur[(size_t)(b*HKV + hkv)*Dn + tid];
    out[(size_t)head*Dn + tid] = o / den;
}

// ---------------------------------------------------------------- launch
extern "C" void kernel_launch(void* const* d_in, const int* in_sizes, int n_in,
                              void* d_out, int out_size)
{
    const float* q        = (const float*)d_in[0];
    const float* k        = (const float*)d_in[1];
    const float* v        = (const float*)d_in[2];
    const float* kv_scale = (const float*)d_in[3];
    const int*   k_cache  = (const int*)  d_in[4];
    const int*   v_cache  = (const int*)  d_in[5];
    const int*   lengths  = (const int*)  d_in[6];
    const int*   timestep = (const int*)  d_in[7];
    float* out = (float*)d_out;

    int write_idx = (out_size >= Bn*Hn*Dn + Bn*Hn*KP) ? 1 : 0;

    rope_kernel<<<Bn*Hn + Bn*HKV, 64>>>(q, k, timestep);
    score_kernel<<<dim3(Pn, Bn*HKV), 128>>>(k_cache, kv_scale, lengths);
    topk_kernel<<<Bn*Hn, 128>>>(out + Bn*Hn*Dn, write_idx);
    attn_part_kernel<<<Bn*Hn*KP, 128>>>(v_cache);
    attn_reduce_kernel<<<Bn*Hn, 128>>>(v, kv_scale, out);
}